// round 15
// baseline (speedup 1.0000x reference)
#include <cuda_runtime.h>
#include <cstdint>
#include <cstddef>

#define BATCH  2
#define SEQ    2048
#define DMODEL 1024
#define NHEADS 16
#define HD     64
#define QKVDIM 3072

// Scratch (allocation-free rule: __device__ globals).
// Lifetimes (stream-ordered):
//   g_act : rounded x  (round..GEMM1)  THEN attention output (attn..GEMM3)
//   g_w   : rounded Wqkv (round..GEMM1) THEN rounded Wd (round2..GEMM3)
__device__ float g_qkv[(size_t)BATCH*SEQ*QKVDIM];    // 50 MB, tf32-rounded
__device__ float g_act[(size_t)BATCH*SEQ*DMODEL];    // 16.8 MB (aliased)
__device__ float g_w[(size_t)QKVDIM*DMODEL];         // 12.6 MB (aliased)

// ===========================================================================
// helpers
// ===========================================================================
__device__ __forceinline__ uint32_t smem_u32(const void* p) {
    uint32_t a;
    asm("{ .reg .u64 t; cvta.to.shared.u64 t, %1; cvt.u32.u64 %0, t; }"
        : "=r"(a) : "l"(p));
    return a;
}
__device__ __forceinline__ uint32_t f2tf(float f) {
    uint32_t r;
    asm("cvt.rna.tf32.f32 %0, %1;" : "=r"(r) : "f"(f));
    return r;
}
__device__ __forceinline__ float ex2(float x) {
    float y;
    asm("ex2.approx.f32 %0, %1;" : "=f"(y) : "f"(x));
    return y;
}
__device__ __forceinline__ void mma_tf32(float c[4],
                                         uint32_t a0, uint32_t a1,
                                         uint32_t a2, uint32_t a3,
                                         uint32_t b0, uint32_t b1)
{
    asm volatile(
        "mma.sync.aligned.m16n8k8.row.col.f32.tf32.tf32.f32 "
        "{%0,%1,%2,%3},{%4,%5,%6,%7},{%8,%9},{%0,%1,%2,%3};"
        : "+f"(c[0]), "+f"(c[1]), "+f"(c[2]), "+f"(c[3])
        : "r"(a0), "r"(a1), "r"(a2), "r"(a3), "r"(b0), "r"(b1));
}
__device__ __forceinline__ void ldsm_x4(uint32_t& r0, uint32_t& r1,
                                        uint32_t& r2, uint32_t& r3,
                                        uint32_t addr)
{
    asm volatile("ldmatrix.sync.aligned.m8n8.x4.shared.b16 {%0,%1,%2,%3}, [%4];"
                 : "=r"(r0), "=r"(r1), "=r"(r2), "=r"(r3) : "r"(addr));
}
#define CP_ASYNC16(dst_u32, src_ptr) \
    asm volatile("cp.async.cg.shared.global [%0], [%1], 16;" \
                 :: "r"(dst_u32), "l"(src_ptr))
#define CP_COMMIT() asm volatile("cp.async.commit_group;" ::: "memory")
#define CP_WAIT2()  asm volatile("cp.async.wait_group 2;" ::: "memory")
#define CP_WAIT0()  asm volatile("cp.async.wait_group 0;" ::: "memory")

// ===========================================================================
// elementwise tf32 pre-rounding (rna)
// ===========================================================================
__global__ __launch_bounds__(256)
void round_tf32_kernel(const float* __restrict__ in, float* __restrict__ out,
                       int n)
{
    int i = (blockIdx.x * 256 + threadIdx.x) * 4;
    if (i < n) {
        float4 v = *(const float4*)(in + i);
        float4 o;
        o.x = __uint_as_float(f2tf(v.x));
        o.y = __uint_as_float(f2tf(v.y));
        o.z = __uint_as_float(f2tf(v.z));
        o.w = __uint_as_float(f2tf(v.w));
        *(float4*)(out + i) = o;
    }
}

// ===========================================================================
// tf32 mma GEMM, 4-stage cp.async pipeline, ldmatrix fragment loads.
// C[M,N] = A[M,K] @ B[N,K]^T + bias[N]; A,B pre-rounded to tf32.
// BM=BN=128, BK=16, 128 threads (4 warps), warp tile 64x64.
// ===========================================================================
#define GSTRIDE 20
#define STAGE_WORDS (128 * GSTRIDE)
#define STAGE_PAIR  (2 * STAGE_WORDS)
#define GEMM_SMEM_BYTES (4 * STAGE_PAIR * 4)   // 81920

__global__ __launch_bounds__(128, 2)
void gemm_mma(const float* __restrict__ A,
              const float* __restrict__ B,
              const float* __restrict__ bias,
              float* __restrict__ C,
              int M, int N, int K, int round_out)
{
    extern __shared__ uint32_t sm[];
    const uint32_t smem_base = smem_u32(sm);

    const int tid  = threadIdx.x;
    const int lane = tid & 31;
    const int wid  = tid >> 5;
    const int g    = lane >> 2;
    const int t    = lane & 3;
    const int wm   = wid >> 1;
    const int wn   = wid & 1;
    const int q    = lane >> 3;      // ldmatrix quad 0..3
    const int iq   = lane & 7;       // row-in-quad

    const int row0 = blockIdx.y * 128;
    const int col0 = blockIdx.x * 128;
    const int NT   = K / 16;

    // --- cp.async staging geometry ---
    const int lr = tid >> 2;
    const int lc = tid & 3;
    const float* Ab = A + (size_t)row0 * K;
    const float* Bb = B + (size_t)col0 * K;
    uint32_t so[4];
    #pragma unroll
    for (int i = 0; i < 4; i++)
        so[i] = ((i * 32 + lr) * GSTRIDE + lc * 4) * 4;

    #define ISSUE_STAGE(kt, s) do { \
        const uint32_t sa = smem_base + (uint32_t)(s) * (STAGE_PAIR * 4); \
        const uint32_t sb = sa + STAGE_WORDS * 4; \
        const int ko = (kt) * 16 + lc * 4; \
        _Pragma("unroll") \
        for (int i = 0; i < 4; i++) { \
            CP_ASYNC16(sa + so[i], Ab + (size_t)(i * 32 + lr) * K + ko); \
            CP_ASYNC16(sb + so[i], Bb + (size_t)(i * 32 + lr) * K + ko); \
        } \
    } while (0)

    // --- ldmatrix lane address offsets (bytes, within a stage) ---
    const uint32_t aoff =
        ((uint32_t)((wm * 64 + (q & 1) * 8 + iq) * GSTRIDE + (q >> 1) * 4)) * 4;
    const uint32_t boff =
        ((uint32_t)((wn * 64 + (q >> 1) * 8 + iq) * GSTRIDE + (q & 1) * 4)) * 4
        + STAGE_WORDS * 4;

    float acc[4][8][4];
    #pragma unroll
    for (int mf = 0; mf < 4; mf++)
        #pragma unroll
        for (int nf = 0; nf < 8; nf++)
            #pragma unroll
            for (int c = 0; c < 4; c++) acc[mf][nf][c] = 0.f;

    ISSUE_STAGE(0, 0); CP_COMMIT();
    ISSUE_STAGE(1, 1); CP_COMMIT();
    ISSUE_STAGE(2, 2); CP_COMMIT();

    for (int kt = 0; kt < NT; kt++) {
        if (kt + 3 < NT) ISSUE_STAGE(kt + 3, (kt + 3) & 3);
        CP_COMMIT();
        CP_WAIT2();
        __syncthreads();

        const uint32_t stage = smem_base + (uint32_t)(kt & 3) * (STAGE_PAIR * 4);
        const uint32_t abase = stage + aoff;
        const uint32_t bbase = stage + boff;

        #pragma unroll
        for (int kk = 0; kk < 16; kk += 8) {
            uint32_t a[4][4], bf[8][2];
            #pragma unroll
            for (int mf = 0; mf < 4; mf++)
                ldsm_x4(a[mf][0], a[mf][1], a[mf][2], a[mf][3],
                        abase + (uint32_t)(mf * 16 * GSTRIDE + kk) * 4);
            #pragma unroll
            for (int nfp = 0; nfp < 4; nfp++)
                ldsm_x4(bf[2*nfp][0], bf[2*nfp][1], bf[2*nfp+1][0], bf[2*nfp+1][1],
                        bbase + (uint32_t)(nfp * 16 * GSTRIDE + kk) * 4);
            #pragma unroll
            for (int mf = 0; mf < 4; mf++)
                #pragma unroll
                for (int nf = 0; nf < 8; nf++)
                    mma_tf32(acc[mf][nf], a[mf][0], a[mf][1], a[mf][2], a[mf][3],
                             bf[nf][0], bf[nf][1]);
        }
        __syncthreads();
    }

    #pragma unroll
    for (int mf = 0; mf < 4; mf++) {
        const int r0 = row0 + wm * 64 + mf * 16 + g;
        #pragma unroll
        for (int nf = 0; nf < 8; nf++) {
            const int col = col0 + wn * 64 + nf * 8 + 2 * t;
            const float b0 = bias[col], b1 = bias[col + 1];
            float v0 = acc[mf][nf][0] + b0, v1 = acc[mf][nf][1] + b1;
            float v2 = acc[mf][nf][2] + b0, v3 = acc[mf][nf][3] + b1;
            if (round_out) {
                v0 = __uint_as_float(f2tf(v0));
                v1 = __uint_as_float(f2tf(v1));
                v2 = __uint_as_float(f2tf(v2));
                v3 = __uint_as_float(f2tf(v3));
            }
            *(float2*)(C + (size_t)r0 * N + col)       = make_float2(v0, v1);
            *(float2*)(C + (size_t)(r0 + 8) * N + col) = make_float2(v2, v3);
        }
    }
}

// ===========================================================================
// tf32 mma causal flash attention (R10 version: XOR swizzle, 3 CTA/SM,
// cp.async K/V, heavy-qt-first 1-D grid).
// ===========================================================================
#define QS_OFF 0
#define KS_OFF (64 * 64)
#define VS_OFF (KS_OFF + 64 * 64)
#define PS_OFF (VS_OFF + 64 * 64)
#define ATTN_SMEM_WORDS (PS_OFF + 64 * 64)
#define ATTN_SMEM_BYTES (ATTN_SMEM_WORDS * 4)   // 65536

__global__ __launch_bounds__(128, 3)
void attn_mma(const float* __restrict__ qkv, float* __restrict__ outp)
{
    extern __shared__ uint32_t smab[];
    uint32_t* Qs = smab + QS_OFF;
    uint32_t* Ks = smab + KS_OFF;
    uint32_t* Vs = smab + VS_OFF;
    uint32_t* Ps = smab + PS_OFF;
    const uint32_t ks_base = smem_u32(Ks);
    const uint32_t vs_base = smem_u32(Vs);

    const int tid  = threadIdx.x;
    const int lane = tid & 31;
    const int w    = tid >> 5;
    const int g    = lane >> 2;
    const int t    = lane & 3;
    const int g4   = g << 2;
    const int t8   = t << 3;

    const int bid = blockIdx.x;
    const int qt  = 31 - (bid >> 5);
    const int yz  = bid & 31;
    const int h   = yz & 15;
    const int b   = yz >> 4;
    const int q0  = qt * 64;

    const float SCALE = 0.125f * 1.44269504088896f;

    {
        const float* qb = qkv + (size_t)(b * SEQ + q0) * QKVDIM + h * HD;
        #pragma unroll
        for (int i = 0; i < 8; i++) {
            int f = i * 128 + tid;
            int row = f >> 4, c4 = (f & 15) * 4;
            int c4s = c4 ^ ((row & 7) << 2);
            float4 v = *(const float4*)(qb + (size_t)row * QKVDIM + c4);
            uint4 u;
            u.x = f2tf(v.x * SCALE); u.y = f2tf(v.y * SCALE);
            u.z = f2tf(v.z * SCALE); u.w = f2tf(v.w * SCALE);
            *(uint4*)&Qs[row * 64 + c4s] = u;
        }
    }

    float m0 = -1e30f, m1 = -1e30f, l0 = 0.f, l1 = 0.f;
    float O[8][4];
    #pragma unroll
    for (int nf = 0; nf < 8; nf++)
        #pragma unroll
        for (int c = 0; c < 4; c++) O[nf][c] = 0.f;

    const int qrow  = (w * 16 + g) * 64;
    const int qrow8 = (w * 16 + g + 8) * 64;

    for (int kv0 = 0; kv0 <= q0; kv0 += 64) {
        __syncthreads();
        {
            const float* kb = qkv + (size_t)(b * SEQ + kv0) * QKVDIM + DMODEL + h * HD;
            const float* vb = kb + DMODEL;
            #pragma unroll
            for (int i = 0; i < 8; i++) {
                int f = i * 128 + tid;
                int row = f >> 4, c4 = (f & 15) * 4;
                int kc4 = c4 ^ ((row & 7) << 2);
                int vc4 = c4 ^ ((row & 3) << 3);
                CP_ASYNC16(ks_base + (uint32_t)(row * 64 + kc4) * 4,
                           kb + (size_t)row * QKVDIM + c4);
                CP_ASYNC16(vs_base + (uint32_t)(row * 64 + vc4) * 4,
                           vb + (size_t)row * QKVDIM + c4);
            }
        }
        CP_COMMIT();
        CP_WAIT0();
        __syncthreads();

        float s[8][4];
        #pragma unroll
        for (int nf = 0; nf < 8; nf++)
            #pragma unroll
            for (int c = 0; c < 4; c++) s[nf][c] = 0.f;

        #pragma unroll
        for (int kk = 0; kk < 64; kk += 8) {
            uint32_t a0 = Qs[qrow  + ((kk + t) ^ g4)];
            uint32_t a1 = Qs[qrow8 + ((kk + t) ^ g4)];
            uint32_t a2 = Qs[qrow  + ((kk + t + 4) ^ g4)];
            uint32_t a3 = Qs[qrow8 + ((kk + t + 4) ^ g4)];
            #pragma unroll
            for (int nf = 0; nf < 8; nf++) {
                uint32_t b0 = Ks[(nf * 8 + g) * 64 + ((kk + t) ^ g4)];
                uint32_t b1 = Ks[(nf * 8 + g) * 64 + ((kk + t + 4) ^ g4)];
                mma_tf32(s[nf], a0, a1, a2, a3, b0, b1);
            }
        }

        const int r0 = q0 + w * 16 + g;
        const int r1 = r0 + 8;
        if (kv0 == q0) {
            #pragma unroll
            for (int nf = 0; nf < 8; nf++) {
                int c0 = kv0 + nf * 8 + 2 * t;
                if (c0     > r0) s[nf][0] = -1e30f;
                if (c0 + 1 > r0) s[nf][1] = -1e30f;
                if (c0     > r1) s[nf][2] = -1e30f;
                if (c0 + 1 > r1) s[nf][3] = -1e30f;
            }
        }

        float rm0 = -1e30f, rm1 = -1e30f;
        #pragma unroll
        for (int nf = 0; nf < 8; nf++) {
            rm0 = fmaxf(rm0, fmaxf(s[nf][0], s[nf][1]));
            rm1 = fmaxf(rm1, fmaxf(s[nf][2], s[nf][3]));
        }
        rm0 = fmaxf(rm0, __shfl_xor_sync(0xffffffffu, rm0, 1));
        rm0 = fmaxf(rm0, __shfl_xor_sync(0xffffffffu, rm0, 2));
        rm1 = fmaxf(rm1, __shfl_xor_sync(0xffffffffu, rm1, 1));
        rm1 = fmaxf(rm1, __shfl_xor_sync(0xffffffffu, rm1, 2));

        float mn0 = fmaxf(m0, rm0), mn1 = fmaxf(m1, rm1);
        float f0 = ex2(m0 - mn0), f1 = ex2(m1 - mn1);
        l0 *= f0; l1 *= f1;
        #pragma unroll
        for (int nf = 0; nf < 8; nf++) {
            O[nf][0] *= f0; O[nf][1] *= f0;
            O[nf][2] *= f1; O[nf][3] *= f1;
        }

        float sum0 = 0.f, sum1 = 0.f;
        #pragma unroll
        for (int nf = 0; nf < 8; nf++) {
            float p0 = ex2(s[nf][0] - mn0);
            float p1 = ex2(s[nf][1] - mn0);
            float p2 = ex2(s[nf][2] - mn1);
            float p3 = ex2(s[nf][3] - mn1);
            sum0 += p0 + p1; sum1 += p2 + p3;
            int cis = (nf * 8 + 2 * t) ^ g4;
            Ps[qrow  + cis] = f2tf(p0); Ps[qrow  + cis + 1] = f2tf(p1);
            Ps[qrow8 + cis] = f2tf(p2); Ps[qrow8 + cis + 1] = f2tf(p3);
        }
        sum0 += __shfl_xor_sync(0xffffffffu, sum0, 1);
        sum0 += __shfl_xor_sync(0xffffffffu, sum0, 2);
        sum1 += __shfl_xor_sync(0xffffffffu, sum1, 1);
        sum1 += __shfl_xor_sync(0xffffffffu, sum1, 2);
        l0 += sum0; l1 += sum1;
        m0 = mn0; m1 = mn1;

        __syncwarp();

        #pragma unroll
        for (int kk = 0; kk < 64; kk += 8) {
            uint32_t a0 = Ps[qrow  + ((kk + t) ^ g4)];
            uint32_t a1 = Ps[qrow8 + ((kk + t) ^ g4)];
            uint32_t a2 = Ps[qrow  + ((kk + t + 4) ^ g4)];
            uint32_t a3 = Ps[qrow8 + ((kk + t + 4) ^ g4)];
            #pragma unroll
            for (int nf = 0; nf < 8; nf++) {
                int col = (nf * 8 + g) ^ t8;
                uint32_t b0 = Vs[(kk + t) * 64 + col];
                uint32_t b1 = Vs[(kk + t + 4) * 64 + col];
                mma_tf32(O[nf], a0, a1, a2, a3, b0, b1);
            }
        }
    }

    const float inv0 = 1.f / l0, inv1 = 1.f / l1;
    const size_t orow0 = (size_t)(b * SEQ + q0 + w * 16 + g);
    const size_t orow1 = orow0 + 8;
    #pragma unroll
    for (int nf = 0; nf < 8; nf++) {
        const int col = h * HD + nf * 8 + 2 * t;
        *(float2*)(outp + orow0 * DMODEL + col) =
            make_float2(__uint_as_float(f2tf(O[nf][0] * inv0)),
                        __uint_as_float(f2tf(O[nf][1] * inv0)));
        *(float2*)(outp + orow1 * DMODEL + col) =
            make_float2(__uint_as_float(f2tf(O[nf][2] * inv1)),
                        __uint_as_float(f2tf(O[nf][3] * inv1)));
    }
}

// ---------------------------------------------------------------------------
// Buffer aliasing plan (stream order makes each reuse safe):
//   g_act: [round x] -> read by GEMM1 ... then attn writes its output here
//   g_w  : [round Wqkv] -> read by GEMM1 ... [round Wd] -> read by GEMM3
// ---------------------------------------------------------------------------
extern "C" void kernel_launch(void* const* d_in, const int* in_sizes, int n_in,
                              void* d_out, int out_size)
{
    const float* x    = (const float*)d_in[0];
    const float* Wqkv = (const float*)d_in[1];
    const float* bqkv = (const float*)d_in[2];
    const float* Wd   = (const float*)d_in[3];
    const float* bd   = (const float*)d_in[4];
    float* out = (float*)d_out;

    float *qkv_buf, *act_buf, *w_buf;
    cudaGetSymbolAddress((void**)&qkv_buf, g_qkv);
    cudaGetSymbolAddress((void**)&act_buf, g_act);
    cudaGetSymbolAddress((void**)&w_buf,   g_w);

    const int M = BATCH * SEQ;   // 4096

    cudaFuncSetAttribute(gemm_mma,
                         cudaFuncAttributeMaxDynamicSharedMemorySize,
                         GEMM_SMEM_BYTES);
    cudaFuncSetAttribute(attn_mma,
                         cudaFuncAttributeMaxDynamicSharedMemorySize,
                         ATTN_SMEM_BYTES);

    const int nx = M * DMODEL, nwq = QKVDIM * DMODEL, nwd = DMODEL * DMODEL;

    // 0) round x and Wqkv
    round_tf32_kernel<<<(nx / 4 + 255) / 256, 256>>>(x, act_buf, nx);
    round_tf32_kernel<<<(nwq / 4 + 255) / 256, 256>>>(Wqkv, w_buf, nwq);

    // 1) QKV projection (writes tf32-rounded qkv); frees act_buf + w_buf
    gemm_mma<<<dim3(QKVDIM / 128, M / 128), 128, GEMM_SMEM_BYTES>>>(
        act_buf, w_buf, bqkv, qkv_buf, M, QKVDIM, DMODEL, 1);

    // 1b) round Wd into the (now free) weight buffer
    round_tf32_kernel<<<(nwd / 4 + 255) / 256, 256>>>(Wd, w_buf, nwd);

    // 2) Causal attention -> act_buf (tf32-rounded)
    attn_mma<<<SEQ / 64 * NHEADS * BATCH, 128, ATTN_SMEM_BYTES>>>(
        qkv_buf, act_buf);

    // 3) Output projection (full fp32 out)
    gemm_mma<<<dim3(DMODEL / 128, M / 128), 128, GEMM_SMEM_BYTES>>>(
        act_buf, w_buf, bd, out, M, DMODEL, DMODEL, 0);
}